// round 8
// baseline (speedup 1.0000x reference)
#include <cuda_runtime.h>
#include <cuda_bf16.h>
#include <cuda_fp16.h>
#include <math.h>

#define MAXN 50000
#define MAXE 800000
#define INC 128

typedef unsigned long long u64;
typedef unsigned int u32;

// ---------------- scratch (no allocation allowed) ----------------
__device__ __align__(16) float g_bufA[MAXN * 128];
__device__ __align__(16) float g_bufB[MAXN * 128];
__device__ float g_dinv[MAXN];
__device__ int   g_deg[MAXN];
__device__ int   g_off[MAXN + 1];
__device__ int   g_col[MAXE];
__device__ int   g_blksum[64];

// ---------------- helpers ----------------
__device__ __forceinline__ void h8f(int4 v, float* f) {
    const __half2* h = reinterpret_cast<const __half2*>(&v);
#pragma unroll
    for (int i = 0; i < 4; i++) {
        float2 t = __half22float2(h[i]);
        f[2 * i] = t.x; f[2 * i + 1] = t.y;
    }
}
__device__ __forceinline__ int4 f8h(const float* f) {
    int4 v;
    __half2* h = reinterpret_cast<__half2*>(&v);
#pragma unroll
    for (int i = 0; i < 4; i++) h[i] = __floats2half2_rn(f[2 * i], f[2 * i + 1]);
    return v;
}

// ---------------- CSR build ----------------
__global__ void k_count(const int* __restrict__ dst, int e) {
    int i = blockIdx.x * blockDim.x + threadIdx.x;
    if (i < e) atomicAdd(&g_deg[dst[i]], 1);
}

__global__ void k_scanA(int n) {
    __shared__ int sm[1024];
    int i = blockIdx.x * 1024 + threadIdx.x;
    int v = (i < n) ? g_deg[i] : 0;
    sm[threadIdx.x] = v;
    __syncthreads();
    for (int s = 1; s < 1024; s <<= 1) {
        int t = (threadIdx.x >= s) ? sm[threadIdx.x - s] : 0;
        __syncthreads();
        sm[threadIdx.x] += t;
        __syncthreads();
    }
    if (i < n) g_off[i + 1] = sm[threadIdx.x];
    if (threadIdx.x == 1023) g_blksum[blockIdx.x] = sm[1023];
}

__global__ void k_scanB(int nb) {
    __shared__ int sm[64];
    int t = threadIdx.x;
    int v = (t < nb) ? g_blksum[t] : 0;
    sm[t] = v;
    __syncthreads();
    for (int s = 1; s < 64; s <<= 1) {
        int u = (t >= s) ? sm[t - s] : 0;
        __syncthreads();
        sm[t] += u;
        __syncthreads();
    }
    if (t < nb) g_blksum[t] = sm[t] - v;  // exclusive
}

__global__ void k_scanC(int n) {
    int i = blockIdx.x * 1024 + threadIdx.x;
    if (i < n) {
        g_off[i + 1] += g_blksum[blockIdx.x];
        g_dinv[i] = rsqrtf((float)(g_deg[i] + 1));
    }
    if (i == 0) g_off[0] = 0;
}

__global__ void k_fill(const int* __restrict__ src, const int* __restrict__ dst, int e) {
    int i = blockIdx.x * blockDim.x + threadIdx.x;
    if (i < e) {
        int d = dst[i];
        int p = atomicSub(&g_deg[d], 1);
        g_col[g_off[d] + p - 1] = src[i];
    }
}

// ---------------- tensor-core GEMM: out[M,NC] = A[M,K] @ W[K,NC] ----------------
template <int K, int NC, bool AF16, bool OUTH, bool BIAS, bool RELU>
__global__ void k_mma(const void* __restrict__ Ap, const float* __restrict__ W,
                      const float* __restrict__ bias, void* __restrict__ outp, int M) {
    constexpr int BM = 128, BN = 64, BK = 32, PAD = 8;
    __shared__ __half As[BM][BK + PAD];
    __shared__ __half Bs[BN][BK + PAD];

    const int tid = threadIdx.x;
    const int wid = tid >> 5, lane = tid & 31;
    const int warp_m = wid & 3, warp_n = wid >> 2;
    const int g = lane >> 2, tig = lane & 3;
    const int row0 = blockIdx.x * BM;
    const int col0 = blockIdx.y * BN;

    float acc[2][4][4];
#pragma unroll
    for (int mt = 0; mt < 2; mt++)
#pragma unroll
        for (int nt = 0; nt < 4; nt++)
#pragma unroll
            for (int i = 0; i < 4; i++) acc[mt][nt][i] = 0.f;

    for (int k0 = 0; k0 < K; k0 += BK) {
#pragma unroll
        for (int it = 0; it < 2; it++) {
            int idx = tid + it * 256;
            int r = idx >> 2, ch = idx & 3;
            int gr = row0 + r;
            int4 val;
            if (gr < M) {
                if (AF16) {
                    const int4* A16 = (const int4*)Ap;
                    val = A16[(size_t)gr * (K / 8) + (k0 >> 3) + ch];
                } else {
                    const float* Af = (const float*)Ap;
                    const float4* p = (const float4*)&Af[(size_t)gr * K + k0 + ch * 8];
                    float4 f0 = p[0], f1 = p[1];
                    __half2* h = (__half2*)&val;
                    h[0] = __floats2half2_rn(f0.x, f0.y);
                    h[1] = __floats2half2_rn(f0.z, f0.w);
                    h[2] = __floats2half2_rn(f1.x, f1.y);
                    h[3] = __floats2half2_rn(f1.z, f1.w);
                }
            } else {
                val = make_int4(0, 0, 0, 0);
            }
            *(int4*)&As[r][ch * 8] = val;
        }
#pragma unroll
        for (int i = 0; i < 8; i++) {
            int lin = tid + i * 256;
            int kk = lin >> 6, n = lin & 63;
            Bs[n][kk] = __float2half(W[(size_t)(k0 + kk) * NC + col0 + n]);
        }
        __syncthreads();

#pragma unroll
        for (int ks = 0; ks < BK; ks += 16) {
            u32 a[2][4], b[4][2];
#pragma unroll
            for (int mt = 0; mt < 2; mt++) {
                int rb = warp_m * 32 + mt * 16 + g;
                a[mt][0] = *(const u32*)&As[rb][ks + 2 * tig];
                a[mt][1] = *(const u32*)&As[rb + 8][ks + 2 * tig];
                a[mt][2] = *(const u32*)&As[rb][ks + 2 * tig + 8];
                a[mt][3] = *(const u32*)&As[rb + 8][ks + 2 * tig + 8];
            }
#pragma unroll
            for (int nt = 0; nt < 4; nt++) {
                int nb = warp_n * 32 + nt * 8 + g;
                b[nt][0] = *(const u32*)&Bs[nb][ks + 2 * tig];
                b[nt][1] = *(const u32*)&Bs[nb][ks + 2 * tig + 8];
            }
#pragma unroll
            for (int mt = 0; mt < 2; mt++)
#pragma unroll
                for (int nt = 0; nt < 4; nt++) {
                    asm volatile(
                        "mma.sync.aligned.m16n8k16.row.col.f32.f16.f16.f32 "
                        "{%0,%1,%2,%3}, {%4,%5,%6,%7}, {%8,%9}, {%0,%1,%2,%3};"
                        : "+f"(acc[mt][nt][0]), "+f"(acc[mt][nt][1]),
                          "+f"(acc[mt][nt][2]), "+f"(acc[mt][nt][3])
                        : "r"(a[mt][0]), "r"(a[mt][1]), "r"(a[mt][2]), "r"(a[mt][3]),
                          "r"(b[nt][0]), "r"(b[nt][1]));
                }
        }
        __syncthreads();
    }

    float* outf = (float*)outp;
    __half* outh = (__half*)outp;
#pragma unroll
    for (int mt = 0; mt < 2; mt++) {
        int r0 = row0 + warp_m * 32 + mt * 16 + g;
#pragma unroll
        for (int nt = 0; nt < 4; nt++) {
            int gc = col0 + warp_n * 32 + nt * 8 + 2 * tig;
            float2 v0 = make_float2(acc[mt][nt][0], acc[mt][nt][1]);
            float2 v1 = make_float2(acc[mt][nt][2], acc[mt][nt][3]);
            if (BIAS) {
                float2 bb = *(const float2*)&bias[gc];
                v0.x += bb.x; v0.y += bb.y; v1.x += bb.x; v1.y += bb.y;
            }
            if (RELU) {
                v0.x = fmaxf(v0.x, 0.f); v0.y = fmaxf(v0.y, 0.f);
                v1.x = fmaxf(v1.x, 0.f); v1.y = fmaxf(v1.y, 0.f);
            }
            if (r0 < M) {
                if (OUTH) *(__half2*)&outh[(size_t)r0 * NC + gc] = __floats2half2_rn(v0.x, v0.y);
                else      *(float2*)&outf[(size_t)r0 * NC + gc] = v0;
            }
            if (r0 + 8 < M) {
                if (OUTH) *(__half2*)&outh[(size_t)(r0 + 8) * NC + gc] = __floats2half2_rn(v1.x, v1.y);
                else      *(float2*)&outf[(size_t)(r0 + 8) * NC + gc] = v1;
            }
        }
    }
}

// ---------------- fused mu/logvar/z MMA: one pass over h2 ----------------
// mu = A@Wm+bm (fp32 out), lv = A@Wl+bl (fp32 out), z = mu+eps*exp(0.5*lv) (fp16 out)
__global__ void k_mulvz(const void* __restrict__ Ap,
                        const float* __restrict__ Wm, const float* __restrict__ bm,
                        const float* __restrict__ Wl, const float* __restrict__ bl,
                        const float* __restrict__ eps,
                        float* __restrict__ out_mu, float* __restrict__ out_lv,
                        __half* __restrict__ zbuf, int M) {
    constexpr int K = 64, NC = 64, BM = 128, BK = 32, PAD = 8;
    __shared__ __half As[BM][BK + PAD];
    __shared__ __half Bm[NC][BK + PAD];
    __shared__ __half Bl[NC][BK + PAD];

    const int tid = threadIdx.x;
    const int wid = tid >> 5, lane = tid & 31;
    const int warp_m = wid & 3, warp_n = wid >> 2;
    const int g = lane >> 2, tig = lane & 3;
    const int row0 = blockIdx.x * BM;

    float am[2][4][4], al[2][4][4];
#pragma unroll
    for (int mt = 0; mt < 2; mt++)
#pragma unroll
        for (int nt = 0; nt < 4; nt++)
#pragma unroll
            for (int i = 0; i < 4; i++) { am[mt][nt][i] = 0.f; al[mt][nt][i] = 0.f; }

    for (int k0 = 0; k0 < K; k0 += BK) {
#pragma unroll
        for (int it = 0; it < 2; it++) {
            int idx = tid + it * 256;
            int r = idx >> 2, ch = idx & 3;
            int gr = row0 + r;
            int4 val = make_int4(0, 0, 0, 0);
            if (gr < M) {
                const int4* A16 = (const int4*)Ap;
                val = A16[(size_t)gr * (K / 8) + (k0 >> 3) + ch];
            }
            *(int4*)&As[r][ch * 8] = val;
        }
#pragma unroll
        for (int i = 0; i < 8; i++) {
            int lin = tid + i * 256;
            int kk = lin >> 6, n = lin & 63;
            Bm[n][kk] = __float2half(Wm[(size_t)(k0 + kk) * NC + n]);
            Bl[n][kk] = __float2half(Wl[(size_t)(k0 + kk) * NC + n]);
        }
        __syncthreads();

#pragma unroll
        for (int ks = 0; ks < BK; ks += 16) {
            u32 a[2][4], b[4][2], c[4][2];
#pragma unroll
            for (int mt = 0; mt < 2; mt++) {
                int rb = warp_m * 32 + mt * 16 + g;
                a[mt][0] = *(const u32*)&As[rb][ks + 2 * tig];
                a[mt][1] = *(const u32*)&As[rb + 8][ks + 2 * tig];
                a[mt][2] = *(const u32*)&As[rb][ks + 2 * tig + 8];
                a[mt][3] = *(const u32*)&As[rb + 8][ks + 2 * tig + 8];
            }
#pragma unroll
            for (int nt = 0; nt < 4; nt++) {
                int nb = warp_n * 32 + nt * 8 + g;
                b[nt][0] = *(const u32*)&Bm[nb][ks + 2 * tig];
                b[nt][1] = *(const u32*)&Bm[nb][ks + 2 * tig + 8];
                c[nt][0] = *(const u32*)&Bl[nb][ks + 2 * tig];
                c[nt][1] = *(const u32*)&Bl[nb][ks + 2 * tig + 8];
            }
#pragma unroll
            for (int mt = 0; mt < 2; mt++)
#pragma unroll
                for (int nt = 0; nt < 4; nt++) {
                    asm volatile(
                        "mma.sync.aligned.m16n8k16.row.col.f32.f16.f16.f32 "
                        "{%0,%1,%2,%3}, {%4,%5,%6,%7}, {%8,%9}, {%0,%1,%2,%3};"
                        : "+f"(am[mt][nt][0]), "+f"(am[mt][nt][1]),
                          "+f"(am[mt][nt][2]), "+f"(am[mt][nt][3])
                        : "r"(a[mt][0]), "r"(a[mt][1]), "r"(a[mt][2]), "r"(a[mt][3]),
                          "r"(b[nt][0]), "r"(b[nt][1]));
                    asm volatile(
                        "mma.sync.aligned.m16n8k16.row.col.f32.f16.f16.f32 "
                        "{%0,%1,%2,%3}, {%4,%5,%6,%7}, {%8,%9}, {%0,%1,%2,%3};"
                        : "+f"(al[mt][nt][0]), "+f"(al[mt][nt][1]),
                          "+f"(al[mt][nt][2]), "+f"(al[mt][nt][3])
                        : "r"(a[mt][0]), "r"(a[mt][1]), "r"(a[mt][2]), "r"(a[mt][3]),
                          "r"(c[nt][0]), "r"(c[nt][1]));
                }
        }
        __syncthreads();
    }

#pragma unroll
    for (int mt = 0; mt < 2; mt++) {
        int rbase = row0 + warp_m * 32 + mt * 16 + g;
#pragma unroll
        for (int nt = 0; nt < 4; nt++) {
            int gc = warp_n * 32 + nt * 8 + 2 * tig;
            float2 bmu = *(const float2*)&bm[gc];
            float2 blv = *(const float2*)&bl[gc];
#pragma unroll
            for (int half = 0; half < 2; half++) {
                int r = rbase + half * 8;
                if (r >= M) continue;
                float2 mu = make_float2(am[mt][nt][2 * half] + bmu.x,
                                        am[mt][nt][2 * half + 1] + bmu.y);
                float2 lv = make_float2(al[mt][nt][2 * half] + blv.x,
                                        al[mt][nt][2 * half + 1] + blv.y);
                float2 ep = *(const float2*)&eps[(size_t)r * NC + gc];
                float2 z = make_float2(mu.x + ep.x * expf(0.5f * lv.x),
                                       mu.y + ep.y * expf(0.5f * lv.y));
                *(float2*)&out_mu[(size_t)r * NC + gc] = mu;
                *(float2*)&out_lv[(size_t)r * NC + gc] = lv;
                *(__half2*)&zbuf[(size_t)r * NC + gc] = __floats2half2_rn(z.x, z.y);
            }
        }
    }
}

// ---------------- pull aggregation over fp16 features (int4 lanes, multi-node warps) ----------------
// out[d] = dinv[d]*(hs[d]*dinv[d] + sum_src hs[src]*dinv[src]) (+bias)(relu)
template <int C, bool BIAS, bool RELU, bool OUTH>
__global__ void k_agg(const int4* __restrict__ hs, const float* __restrict__ bias,
                      void* __restrict__ outp, int n) {
    constexpr int LPN = C / 8;               // int4 per node row (C halves = C*2 bytes / 16)
    constexpr int NPW = 32 / LPN;            // nodes per warp
    constexpr int NPB = 8 * NPW;             // nodes per 256-thread block
    const int tid = threadIdx.x;
    const int lane = tid & 31;
    const int sub = lane & (LPN - 1);        // int4 index within row
    const int node = blockIdx.x * NPB + (tid >> 5) * NPW + (lane / LPN);
    if (node >= n) return;

    float di = g_dinv[node];
    float acc[8], f[8];
    h8f(hs[(size_t)node * LPN + sub], f);
#pragma unroll
    for (int i = 0; i < 8; i++) acc[i] = f[i] * di;

    int b0 = g_off[node], b1 = g_off[node + 1];
    int j = b0;
    for (; j + 3 < b1; j += 4) {
        int s0 = g_col[j], s1 = g_col[j + 1], s2 = g_col[j + 2], s3 = g_col[j + 3];
        float d0 = g_dinv[s0], d1 = g_dinv[s1], d2 = g_dinv[s2], d3 = g_dinv[s3];
        int4 v0 = hs[(size_t)s0 * LPN + sub];
        int4 v1 = hs[(size_t)s1 * LPN + sub];
        int4 v2 = hs[(size_t)s2 * LPN + sub];
        int4 v3 = hs[(size_t)s3 * LPN + sub];
        float f0[8], f1[8], f2[8], f3[8];
        h8f(v0, f0); h8f(v1, f1); h8f(v2, f2); h8f(v3, f3);
#pragma unroll
        for (int i = 0; i < 8; i++)
            acc[i] += f0[i] * d0 + f1[i] * d1 + f2[i] * d2 + f3[i] * d3;
    }
    for (; j < b1; j++) {
        int s = g_col[j];
        float ds = g_dinv[s];
        h8f(hs[(size_t)s * LPN + sub], f);
#pragma unroll
        for (int i = 0; i < 8; i++) acc[i] += f[i] * ds;
    }
#pragma unroll
    for (int i = 0; i < 8; i++) acc[i] *= di;
    if (BIAS) {
        float4 ba = reinterpret_cast<const float4*>(bias)[2 * sub];
        float4 bb = reinterpret_cast<const float4*>(bias)[2 * sub + 1];
        acc[0] += ba.x; acc[1] += ba.y; acc[2] += ba.z; acc[3] += ba.w;
        acc[4] += bb.x; acc[5] += bb.y; acc[6] += bb.z; acc[7] += bb.w;
    }
    if (RELU) {
#pragma unroll
        for (int i = 0; i < 8; i++) acc[i] = fmaxf(acc[i], 0.f);
    }
    if (OUTH) {
        reinterpret_cast<int4*>(outp)[(size_t)node * LPN + sub] = f8h(acc);
    } else {
        float4* o = reinterpret_cast<float4*>(outp);
        o[(size_t)node * (2 * LPN) + 2 * sub]     = make_float4(acc[0], acc[1], acc[2], acc[3]);
        o[(size_t)node * (2 * LPN) + 2 * sub + 1] = make_float4(acc[4], acc[5], acc[6], acc[7]);
    }
}

extern "C" void kernel_launch(void* const* d_in, const int* in_sizes, int n_in,
                              void* d_out, int out_size) {
    const float* x    = (const float*)d_in[0];
    const int*   ei   = (const int*)d_in[1];
    const float* eps  = (const float*)d_in[2];
    const float* W_e1 = (const float*)d_in[3];
    const float* b_e1 = (const float*)d_in[4];
    const float* W_e2 = (const float*)d_in[5];
    const float* b_e2 = (const float*)d_in[6];
    const float* W_mu = (const float*)d_in[7];
    const float* b_mu = (const float*)d_in[8];
    const float* W_lv = (const float*)d_in[9];
    const float* b_lv = (const float*)d_in[10];
    const float* W_d1 = (const float*)d_in[11];
    const float* b_d1 = (const float*)d_in[12];
    const float* W_d2 = (const float*)d_in[13];
    const float* b_d2 = (const float*)d_in[14];

    int N = in_sizes[0] / INC;
    int E = in_sizes[1] / 2;
    const int* src = ei;
    const int* dst = ei + E;

    float* out    = (float*)d_out;
    float* out_d  = out;
    float* out_mu = out + (size_t)N * 128;
    float* out_lv = out_mu + (size_t)N * 64;

    float* bufA; float* bufB;
    cudaGetSymbolAddress((void**)&bufA, g_bufA);
    cudaGetSymbolAddress((void**)&bufB, g_bufB);
    int4* hA = (int4*)bufA;
    int4* hB = (int4*)bufB;

    static cudaStream_t s2 = nullptr;
    static cudaEvent_t evF = nullptr, evJ = nullptr;
    if (!s2) {
        cudaStreamCreateWithFlags(&s2, cudaStreamNonBlocking);
        cudaEventCreateWithFlags(&evF, cudaEventDisableTiming);
        cudaEventCreateWithFlags(&evJ, cudaEventDisableTiming);
    }

    int nbScan = (N + 1023) / 1024;
    int mBlk = (N + 127) / 128;

    // ---- CSR build on side stream (overlaps e1 GEMM) ----
    cudaEventRecord(evF, 0);
    cudaStreamWaitEvent(s2, evF, 0);
    k_count<<<(E + 255) / 256, 256, 0, s2>>>(dst, E);
    k_scanA<<<nbScan, 1024, 0, s2>>>(N);
    k_scanB<<<1, 64, 0, s2>>>(nbScan);
    k_scanC<<<nbScan, 1024, 0, s2>>>(N);
    k_fill<<<(E + 255) / 256, 256, 0, s2>>>(src, dst, E);
    cudaEventRecord(evJ, s2);

    // ---- encoder conv1 GEMM: hs = x@W_e1 -> fp16 hA ----
    k_mma<128, 128, false, true, false, false><<<dim3(mBlk, 2), 256>>>(
        x, W_e1, nullptr, hA, N);

    cudaStreamWaitEvent(0, evJ, 0);

    // ---- h1 = relu(Â hs + b_e1) -> fp16 hB ---- (C=128: 2 nodes/warp, 16 nodes/block)
    k_agg<128, true, true, true><<<(N + 15) / 16, 256>>>(hA, b_e1, hB, N);

    // ---- encoder conv2: hs = h1@W_e2 -> fp16 hA ; h2 = Â hs + b_e2 -> fp16 hB ----
    k_mma<128, 64, true, true, false, false><<<dim3(mBlk, 1), 256>>>(
        hB, W_e2, nullptr, hA, N);
    k_agg<64, true, false, true><<<(N + 31) / 32, 256>>>(hA, b_e2, hB, N);

    // ---- fused mu/logvar/z: mu,lv -> out (fp32) ; z -> fp16 hA ----
    k_mulvz<<<mBlk, 256>>>(hB, W_mu, b_mu, W_lv, b_lv, eps,
                           out_mu, out_lv, (__half*)hA, N);

    // ---- decoder conv1 (reordered): t = Â z -> fp16 hB ; d1 = relu(t@W_d1+b) -> fp16 hA ----
    k_agg<64, false, false, true><<<(N + 31) / 32, 256>>>(hA, nullptr, hB, N);
    k_mma<64, 128, true, true, true, true><<<dim3(mBlk, 2), 256>>>(
        hB, W_d1, b_d1, hA, N);

    // ---- decoder conv2: hs = d1@W_d2 -> fp16 hB ; d = Â hs + b_d2 -> fp32 out ----
    k_mma<128, 128, true, true, false, false><<<dim3(mBlk, 2), 256>>>(
        hA, W_d2, nullptr, hB, N);
    k_agg<128, true, false, false><<<(N + 15) / 16, 256>>>(hB, b_d2, out_d, N);
}

// round 9
// speedup vs baseline: 1.3444x; 1.3444x over previous
#include <cuda_runtime.h>
#include <cuda_bf16.h>
#include <cuda_fp16.h>
#include <math.h>

#define MAXN 50000
#define MAXE 800000
#define INC 128

typedef unsigned long long u64;
typedef unsigned int u32;

// ---------------- scratch (no allocation allowed) ----------------
__device__ __align__(16) float g_bufA[MAXN * 128];
__device__ __align__(16) float g_bufB[MAXN * 128];
__device__ float g_dinv[MAXN];
__device__ int   g_deg[MAXN];
__device__ int   g_off[MAXN + 1];
__device__ int   g_col[MAXE];
__device__ int   g_blksum[64];

// ---------------- helpers ----------------
__device__ __forceinline__ float4 h4f(u64 v) {
    __half2 a = reinterpret_cast<__half2*>(&v)[0];
    __half2 b = reinterpret_cast<__half2*>(&v)[1];
    float2 fa = __half22float2(a), fb = __half22float2(b);
    return make_float4(fa.x, fa.y, fb.x, fb.y);
}
__device__ __forceinline__ u64 f4h(float4 v) {
    u64 r;
    reinterpret_cast<__half2*>(&r)[0] = __floats2half2_rn(v.x, v.y);
    reinterpret_cast<__half2*>(&r)[1] = __floats2half2_rn(v.z, v.w);
    return r;
}

// ---------------- CSR build ----------------
__global__ void k_count(const int* __restrict__ dst, int e) {
    int i = blockIdx.x * blockDim.x + threadIdx.x;
    if (i < e) atomicAdd(&g_deg[dst[i]], 1);
}

__global__ void k_scanA(int n) {
    __shared__ int sm[1024];
    int i = blockIdx.x * 1024 + threadIdx.x;
    int v = (i < n) ? g_deg[i] : 0;
    sm[threadIdx.x] = v;
    __syncthreads();
    for (int s = 1; s < 1024; s <<= 1) {
        int t = (threadIdx.x >= s) ? sm[threadIdx.x - s] : 0;
        __syncthreads();
        sm[threadIdx.x] += t;
        __syncthreads();
    }
    if (i < n) g_off[i + 1] = sm[threadIdx.x];
    if (threadIdx.x == 1023) g_blksum[blockIdx.x] = sm[1023];
}

__global__ void k_scanB(int nb) {
    __shared__ int sm[64];
    int t = threadIdx.x;
    int v = (t < nb) ? g_blksum[t] : 0;
    sm[t] = v;
    __syncthreads();
    for (int s = 1; s < 64; s <<= 1) {
        int u = (t >= s) ? sm[t - s] : 0;
        __syncthreads();
        sm[t] += u;
        __syncthreads();
    }
    if (t < nb) g_blksum[t] = sm[t] - v;  // exclusive
}

__global__ void k_scanC(int n) {
    int i = blockIdx.x * 1024 + threadIdx.x;
    if (i < n) {
        g_off[i + 1] += g_blksum[blockIdx.x];
        g_dinv[i] = rsqrtf((float)(g_deg[i] + 1));
    }
    if (i == 0) g_off[0] = 0;
}

__global__ void k_fill(const int* __restrict__ src, const int* __restrict__ dst, int e) {
    int i = blockIdx.x * blockDim.x + threadIdx.x;
    if (i < e) {
        int d = dst[i];
        int p = atomicSub(&g_deg[d], 1);
        g_col[g_off[d] + p - 1] = src[i];
    }
}

// ---------------- tensor-core GEMM: out[M,NC] = A[M,K] @ W[K,NC] ----------------
template <int K, int NC, bool AF16, bool OUTH, bool BIAS, bool RELU>
__global__ void k_mma(const void* __restrict__ Ap, const float* __restrict__ W,
                      const float* __restrict__ bias, void* __restrict__ outp, int M) {
    constexpr int BM = 128, BN = 64, BK = 32, PAD = 8;
    __shared__ __half As[BM][BK + PAD];
    __shared__ __half Bs[BN][BK + PAD];

    const int tid = threadIdx.x;
    const int wid = tid >> 5, lane = tid & 31;
    const int warp_m = wid & 3, warp_n = wid >> 2;
    const int g = lane >> 2, tig = lane & 3;
    const int row0 = blockIdx.x * BM;
    const int col0 = blockIdx.y * BN;

    float acc[2][4][4];
#pragma unroll
    for (int mt = 0; mt < 2; mt++)
#pragma unroll
        for (int nt = 0; nt < 4; nt++)
#pragma unroll
            for (int i = 0; i < 4; i++) acc[mt][nt][i] = 0.f;

    for (int k0 = 0; k0 < K; k0 += BK) {
#pragma unroll
        for (int it = 0; it < 2; it++) {
            int idx = tid + it * 256;
            int r = idx >> 2, ch = idx & 3;
            int gr = row0 + r;
            int4 val;
            if (gr < M) {
                if (AF16) {
                    const int4* A16 = (const int4*)Ap;
                    val = A16[(size_t)gr * (K / 8) + (k0 >> 3) + ch];
                } else {
                    const float* Af = (const float*)Ap;
                    const float4* p = (const float4*)&Af[(size_t)gr * K + k0 + ch * 8];
                    float4 f0 = p[0], f1 = p[1];
                    __half2* h = (__half2*)&val;
                    h[0] = __floats2half2_rn(f0.x, f0.y);
                    h[1] = __floats2half2_rn(f0.z, f0.w);
                    h[2] = __floats2half2_rn(f1.x, f1.y);
                    h[3] = __floats2half2_rn(f1.z, f1.w);
                }
            } else {
                val = make_int4(0, 0, 0, 0);
            }
            *(int4*)&As[r][ch * 8] = val;
        }
#pragma unroll
        for (int i = 0; i < 8; i++) {
            int lin = tid + i * 256;
            int kk = lin >> 6, n = lin & 63;
            Bs[n][kk] = __float2half(W[(size_t)(k0 + kk) * NC + col0 + n]);
        }
        __syncthreads();

#pragma unroll
        for (int ks = 0; ks < BK; ks += 16) {
            u32 a[2][4], b[4][2];
#pragma unroll
            for (int mt = 0; mt < 2; mt++) {
                int rb = warp_m * 32 + mt * 16 + g;
                a[mt][0] = *(const u32*)&As[rb][ks + 2 * tig];
                a[mt][1] = *(const u32*)&As[rb + 8][ks + 2 * tig];
                a[mt][2] = *(const u32*)&As[rb][ks + 2 * tig + 8];
                a[mt][3] = *(const u32*)&As[rb + 8][ks + 2 * tig + 8];
            }
#pragma unroll
            for (int nt = 0; nt < 4; nt++) {
                int nb = warp_n * 32 + nt * 8 + g;
                b[nt][0] = *(const u32*)&Bs[nb][ks + 2 * tig];
                b[nt][1] = *(const u32*)&Bs[nb][ks + 2 * tig + 8];
            }
#pragma unroll
            for (int mt = 0; mt < 2; mt++)
#pragma unroll
                for (int nt = 0; nt < 4; nt++) {
                    asm volatile(
                        "mma.sync.aligned.m16n8k16.row.col.f32.f16.f16.f32 "
                        "{%0,%1,%2,%3}, {%4,%5,%6,%7}, {%8,%9}, {%0,%1,%2,%3};"
                        : "+f"(acc[mt][nt][0]), "+f"(acc[mt][nt][1]),
                          "+f"(acc[mt][nt][2]), "+f"(acc[mt][nt][3])
                        : "r"(a[mt][0]), "r"(a[mt][1]), "r"(a[mt][2]), "r"(a[mt][3]),
                          "r"(b[nt][0]), "r"(b[nt][1]));
                }
        }
        __syncthreads();
    }

    float* outf = (float*)outp;
    __half* outh = (__half*)outp;
#pragma unroll
    for (int mt = 0; mt < 2; mt++) {
        int r0 = row0 + warp_m * 32 + mt * 16 + g;
#pragma unroll
        for (int nt = 0; nt < 4; nt++) {
            int gc = col0 + warp_n * 32 + nt * 8 + 2 * tig;
            float2 v0 = make_float2(acc[mt][nt][0], acc[mt][nt][1]);
            float2 v1 = make_float2(acc[mt][nt][2], acc[mt][nt][3]);
            if (BIAS) {
                float2 bb = *(const float2*)&bias[gc];
                v0.x += bb.x; v0.y += bb.y; v1.x += bb.x; v1.y += bb.y;
            }
            if (RELU) {
                v0.x = fmaxf(v0.x, 0.f); v0.y = fmaxf(v0.y, 0.f);
                v1.x = fmaxf(v1.x, 0.f); v1.y = fmaxf(v1.y, 0.f);
            }
            if (r0 < M) {
                if (OUTH) *(__half2*)&outh[(size_t)r0 * NC + gc] = __floats2half2_rn(v0.x, v0.y);
                else      *(float2*)&outf[(size_t)r0 * NC + gc] = v0;
            }
            if (r0 + 8 < M) {
                if (OUTH) *(__half2*)&outh[(size_t)(r0 + 8) * NC + gc] = __floats2half2_rn(v1.x, v1.y);
                else      *(float2*)&outf[(size_t)(r0 + 8) * NC + gc] = v1;
            }
        }
    }
}

// ---------------- fused mu/logvar/z MMA: one pass over h2 ----------------
// mu = A@Wm+bm (fp32 out), lv = A@Wl+bl (fp32 out), z = mu+eps*exp(0.5*lv) (fp16 out)
__global__ void k_mulvz(const void* __restrict__ Ap,
                        const float* __restrict__ Wm, const float* __restrict__ bm,
                        const float* __restrict__ Wl, const float* __restrict__ bl,
                        const float* __restrict__ eps,
                        float* __restrict__ out_mu, float* __restrict__ out_lv,
                        __half* __restrict__ zbuf, int M) {
    constexpr int K = 64, NC = 64, BM = 128, BK = 32, PAD = 8;
    __shared__ __half As[BM][BK + PAD];
    __shared__ __half Bm[NC][BK + PAD];
    __shared__ __half Bl[NC][BK + PAD];

    const int tid = threadIdx.x;
    const int wid = tid >> 5, lane = tid & 31;
    const int warp_m = wid & 3, warp_n = wid >> 2;
    const int g = lane >> 2, tig = lane & 3;
    const int row0 = blockIdx.x * BM;

    float am[2][4][4], al[2][4][4];
#pragma unroll
    for (int mt = 0; mt < 2; mt++)
#pragma unroll
        for (int nt = 0; nt < 4; nt++)
#pragma unroll
            for (int i = 0; i < 4; i++) { am[mt][nt][i] = 0.f; al[mt][nt][i] = 0.f; }

    for (int k0 = 0; k0 < K; k0 += BK) {
#pragma unroll
        for (int it = 0; it < 2; it++) {
            int idx = tid + it * 256;
            int r = idx >> 2, ch = idx & 3;
            int gr = row0 + r;
            int4 val = make_int4(0, 0, 0, 0);
            if (gr < M) {
                const int4* A16 = (const int4*)Ap;
                val = A16[(size_t)gr * (K / 8) + (k0 >> 3) + ch];
            }
            *(int4*)&As[r][ch * 8] = val;
        }
#pragma unroll
        for (int i = 0; i < 8; i++) {
            int lin = tid + i * 256;
            int kk = lin >> 6, n = lin & 63;
            Bm[n][kk] = __float2half(Wm[(size_t)(k0 + kk) * NC + n]);
            Bl[n][kk] = __float2half(Wl[(size_t)(k0 + kk) * NC + n]);
        }
        __syncthreads();

#pragma unroll
        for (int ks = 0; ks < BK; ks += 16) {
            u32 a[2][4], b[4][2], c[4][2];
#pragma unroll
            for (int mt = 0; mt < 2; mt++) {
                int rb = warp_m * 32 + mt * 16 + g;
                a[mt][0] = *(const u32*)&As[rb][ks + 2 * tig];
                a[mt][1] = *(const u32*)&As[rb + 8][ks + 2 * tig];
                a[mt][2] = *(const u32*)&As[rb][ks + 2 * tig + 8];
                a[mt][3] = *(const u32*)&As[rb + 8][ks + 2 * tig + 8];
            }
#pragma unroll
            for (int nt = 0; nt < 4; nt++) {
                int nb = warp_n * 32 + nt * 8 + g;
                b[nt][0] = *(const u32*)&Bm[nb][ks + 2 * tig];
                b[nt][1] = *(const u32*)&Bm[nb][ks + 2 * tig + 8];
                c[nt][0] = *(const u32*)&Bl[nb][ks + 2 * tig];
                c[nt][1] = *(const u32*)&Bl[nb][ks + 2 * tig + 8];
            }
#pragma unroll
            for (int mt = 0; mt < 2; mt++)
#pragma unroll
                for (int nt = 0; nt < 4; nt++) {
                    asm volatile(
                        "mma.sync.aligned.m16n8k16.row.col.f32.f16.f16.f32 "
                        "{%0,%1,%2,%3}, {%4,%5,%6,%7}, {%8,%9}, {%0,%1,%2,%3};"
                        : "+f"(am[mt][nt][0]), "+f"(am[mt][nt][1]),
                          "+f"(am[mt][nt][2]), "+f"(am[mt][nt][3])
                        : "r"(a[mt][0]), "r"(a[mt][1]), "r"(a[mt][2]), "r"(a[mt][3]),
                          "r"(b[nt][0]), "r"(b[nt][1]));
                    asm volatile(
                        "mma.sync.aligned.m16n8k16.row.col.f32.f16.f16.f32 "
                        "{%0,%1,%2,%3}, {%4,%5,%6,%7}, {%8,%9}, {%0,%1,%2,%3};"
                        : "+f"(al[mt][nt][0]), "+f"(al[mt][nt][1]),
                          "+f"(al[mt][nt][2]), "+f"(al[mt][nt][3])
                        : "r"(a[mt][0]), "r"(a[mt][1]), "r"(a[mt][2]), "r"(a[mt][3]),
                          "r"(c[nt][0]), "r"(c[nt][1]));
                }
        }
        __syncthreads();
    }

#pragma unroll
    for (int mt = 0; mt < 2; mt++) {
        int rbase = row0 + warp_m * 32 + mt * 16 + g;
#pragma unroll
        for (int nt = 0; nt < 4; nt++) {
            int gc = warp_n * 32 + nt * 8 + 2 * tig;
            float2 bmu = *(const float2*)&bm[gc];
            float2 blv = *(const float2*)&bl[gc];
#pragma unroll
            for (int hh = 0; hh < 2; hh++) {
                int r = rbase + hh * 8;
                if (r >= M) continue;
                float2 mu = make_float2(am[mt][nt][2 * hh] + bmu.x,
                                        am[mt][nt][2 * hh + 1] + bmu.y);
                float2 lv = make_float2(al[mt][nt][2 * hh] + blv.x,
                                        al[mt][nt][2 * hh + 1] + blv.y);
                float2 ep = *(const float2*)&eps[(size_t)r * NC + gc];
                float2 z = make_float2(mu.x + ep.x * expf(0.5f * lv.x),
                                       mu.y + ep.y * expf(0.5f * lv.y));
                *(float2*)&out_mu[(size_t)r * NC + gc] = mu;
                *(float2*)&out_lv[(size_t)r * NC + gc] = lv;
                *(__half2*)&zbuf[(size_t)r * NC + gc] = __floats2half2_rn(z.x, z.y);
            }
        }
    }
}

// ---------------- pull aggregation over fp16 features (R4 proven form) ----------------
// out[d] = dinv[d] * ( hs[d]*dinv[d] + sum_src hs[src]*dinv[src] ) (+bias)(relu)
template <int C, bool BIAS, bool RELU, bool OUTH>
__global__ void k_agg(const u64* __restrict__ hs, const float* __restrict__ bias,
                      void* __restrict__ outp, int n) {
    constexpr int L = C / 4;
    int lane = threadIdx.x;
    int node = blockIdx.x * blockDim.y + threadIdx.y;
    if (node >= n) return;
    float di = g_dinv[node];
    float4 sv = h4f(hs[(size_t)node * L + lane]);
    float4 acc = make_float4(sv.x * di, sv.y * di, sv.z * di, sv.w * di);
    int b0 = g_off[node], b1 = g_off[node + 1];
    int j = b0;
    for (; j + 3 < b1; j += 4) {
        int s0 = g_col[j], s1 = g_col[j + 1], s2 = g_col[j + 2], s3 = g_col[j + 3];
        float d0 = g_dinv[s0], d1 = g_dinv[s1], d2 = g_dinv[s2], d3 = g_dinv[s3];
        float4 v0 = h4f(hs[(size_t)s0 * L + lane]);
        float4 v1 = h4f(hs[(size_t)s1 * L + lane]);
        float4 v2 = h4f(hs[(size_t)s2 * L + lane]);
        float4 v3 = h4f(hs[(size_t)s3 * L + lane]);
        acc.x += v0.x * d0 + v1.x * d1 + v2.x * d2 + v3.x * d3;
        acc.y += v0.y * d0 + v1.y * d1 + v2.y * d2 + v3.y * d3;
        acc.z += v0.z * d0 + v1.z * d1 + v2.z * d2 + v3.z * d3;
        acc.w += v0.w * d0 + v1.w * d1 + v2.w * d2 + v3.w * d3;
    }
    for (; j < b1; j++) {
        int s = g_col[j];
        float ds = g_dinv[s];
        float4 v = h4f(hs[(size_t)s * L + lane]);
        acc.x += v.x * ds; acc.y += v.y * ds; acc.z += v.z * ds; acc.w += v.w * ds;
    }
    float4 o = make_float4(acc.x * di, acc.y * di, acc.z * di, acc.w * di);
    if (BIAS) {
        float4 bb = reinterpret_cast<const float4*>(bias)[lane];
        o.x += bb.x; o.y += bb.y; o.z += bb.z; o.w += bb.w;
    }
    if (RELU) {
        o.x = fmaxf(o.x, 0.f); o.y = fmaxf(o.y, 0.f);
        o.z = fmaxf(o.z, 0.f); o.w = fmaxf(o.w, 0.f);
    }
    if (OUTH) reinterpret_cast<u64*>(outp)[(size_t)node * L + lane] = f4h(o);
    else      reinterpret_cast<float4*>(outp)[(size_t)node * L + lane] = o;
}

extern "C" void kernel_launch(void* const* d_in, const int* in_sizes, int n_in,
                              void* d_out, int out_size) {
    const float* x    = (const float*)d_in[0];
    const int*   ei   = (const int*)d_in[1];
    const float* eps  = (const float*)d_in[2];
    const float* W_e1 = (const float*)d_in[3];
    const float* b_e1 = (const float*)d_in[4];
    const float* W_e2 = (const float*)d_in[5];
    const float* b_e2 = (const float*)d_in[6];
    const float* W_mu = (const float*)d_in[7];
    const float* b_mu = (const float*)d_in[8];
    const float* W_lv = (const float*)d_in[9];
    const float* b_lv = (const float*)d_in[10];
    const float* W_d1 = (const float*)d_in[11];
    const float* b_d1 = (const float*)d_in[12];
    const float* W_d2 = (const float*)d_in[13];
    const float* b_d2 = (const float*)d_in[14];

    int N = in_sizes[0] / INC;
    int E = in_sizes[1] / 2;
    const int* src = ei;
    const int* dst = ei + E;

    float* out    = (float*)d_out;
    float* out_d  = out;
    float* out_mu = out + (size_t)N * 128;
    float* out_lv = out_mu + (size_t)N * 64;

    float* bufA; float* bufB;
    cudaGetSymbolAddress((void**)&bufA, g_bufA);
    cudaGetSymbolAddress((void**)&bufB, g_bufB);
    u64* hA = (u64*)bufA;
    u64* hB = (u64*)bufB;

    static cudaStream_t s2 = nullptr;
    static cudaEvent_t evF = nullptr, evJ = nullptr;
    if (!s2) {
        cudaStreamCreateWithFlags(&s2, cudaStreamNonBlocking);
        cudaEventCreateWithFlags(&evF, cudaEventDisableTiming);
        cudaEventCreateWithFlags(&evJ, cudaEventDisableTiming);
    }

    int nbScan = (N + 1023) / 1024;
    int mBlk = (N + 127) / 128;

    // ---- CSR build on side stream (overlaps e1 GEMM) ----
    cudaEventRecord(evF, 0);
    cudaStreamWaitEvent(s2, evF, 0);
    k_count<<<(E + 255) / 256, 256, 0, s2>>>(dst, E);
    k_scanA<<<nbScan, 1024, 0, s2>>>(N);
    k_scanB<<<1, 64, 0, s2>>>(nbScan);
    k_scanC<<<nbScan, 1024, 0, s2>>>(N);
    k_fill<<<(E + 255) / 256, 256, 0, s2>>>(src, dst, E);
    cudaEventRecord(evJ, s2);

    // ---- encoder conv1 GEMM: hs = x@W_e1 -> fp16 hA ----
    k_mma<128, 128, false, true, false, false><<<dim3(mBlk, 2), 256>>>(
        x, W_e1, nullptr, hA, N);

    cudaStreamWaitEvent(0, evJ, 0);

    // ---- h1 = relu(Â hs + b_e1) -> fp16 hB ----
    k_agg<128, true, true, true><<<(N + 7) / 8, dim3(32, 8)>>>(hA, b_e1, hB, N);

    // ---- encoder conv2: hs = h1@W_e2 -> fp16 hA ; h2 = Â hs + b_e2 -> fp16 hB ----
    k_mma<128, 64, true, true, false, false><<<dim3(mBlk, 1), 256>>>(
        hB, W_e2, nullptr, hA, N);
    k_agg<64, true, false, true><<<(N + 15) / 16, dim3(16, 16)>>>(hA, b_e2, hB, N);

    // ---- fused mu/logvar/z: mu,lv -> out (fp32) ; z -> fp16 hA ----
    k_mulvz<<<mBlk, 256>>>(hB, W_mu, b_mu, W_lv, b_lv, eps,
                           out_mu, out_lv, (__half*)hA, N);

    // ---- decoder conv1 (reordered): t = Â z -> fp16 hB ; d1 = relu(t@W_d1+b) -> fp16 hA ----
    k_agg<64, false, false, true><<<(N + 15) / 16, dim3(16, 16)>>>(hA, nullptr, hB, N);
    k_mma<64, 128, true, true, true, true><<<dim3(mBlk, 2), 256>>>(
        hB, W_d1, b_d1, hA, N);

    // ---- decoder conv2: hs = d1@W_d2 -> fp16 hB ; d = Â hs + b_d2 -> fp32 out ----
    k_mma<128, 128, true, true, false, false><<<dim3(mBlk, 2), 256>>>(
        hA, W_d2, nullptr, hB, N);
    k_agg<128, true, false, false><<<(N + 7) / 8, dim3(32, 8)>>>(hB, b_d2, out_d, N);
}